// round 8
// baseline (speedup 1.0000x reference)
#include <cuda_runtime.h>
#include <cstdint>

#define BB 128
#define TT 256
#define DD 512
#define HH 1024
#define OO 1024
#define NGC 4096  // 4*H

// ---------------- device scratch (allocation-free contract) ----------------
__device__ float g_xproj[(size_t)TT * BB * NGC];  // [t][b][4H], 512 MB
__device__ float g_h[2][BB * HH];                 // ping-pong hidden state
__device__ float g_c[BB * HH];                    // cell state

// ---------------- helpers ----------------
__device__ __forceinline__ float to_tf32(float x) {
    uint32_t u;
    asm("cvt.rna.tf32.f32 %0, %1;" : "=r"(u) : "f"(x));
    return __uint_as_float(u);
}
__device__ __forceinline__ uint32_t fasu(float x) { return __float_as_uint(x); }

__device__ __forceinline__ void mma8(float* c, const uint32_t* a, const uint32_t* b) {
    asm volatile(
        "mma.sync.aligned.m16n8k8.row.col.f32.tf32.tf32.f32 "
        "{%0,%1,%2,%3}, {%4,%5,%6,%7}, {%8,%9}, {%0,%1,%2,%3};\n"
        : "+f"(c[0]), "+f"(c[1]), "+f"(c[2]), "+f"(c[3])
        : "r"(a[0]), "r"(a[1]), "r"(a[2]), "r"(a[3]), "r"(b[0]), "r"(b[1]));
}

__device__ __forceinline__ float sigm(float x) { return 1.f / (1.f + __expf(-x)); }
__device__ __forceinline__ float tanhx(float x) { return 1.f - 2.f / (1.f + __expf(2.f * x)); }

// ---------------- init: zero h0 and c0 ----------------
__global__ void lstm79_init() {
    int i = blockIdx.x * blockDim.x + threadIdx.x;  // grid 512*256 = BB*HH exactly
    g_h[0][i] = 0.f;
    g_c[i] = 0.f;
}

// ---------------- kernel 1: xproj = x @ Wx^T + b, scattered to [t][b][4H] ----
#define G1_LD 36                 // padded smem row stride (floats), 144B aligned
#define G1_AST (128 * G1_LD)

__global__ void __launch_bounds__(256, 1)
lstm79_xproj(const float* __restrict__ x, const float* __restrict__ wx,
             const float* __restrict__ bias) {
    extern __shared__ float smem[];
    float* As = smem;               // [2][128][36]
    float* Bs = smem + 2 * G1_AST;  // [2][128][36]

    const int tid = threadIdx.x;
    const int l = tid & 31;
    const int w = tid >> 5;
    const int wm = w >> 2;  // 0..1 : 64-row warp band
    const int wn = w & 3;   // 0..3 : 32-col warp band
    const int row0 = blockIdx.y * 128;  // row r = b*T + t  (x layout)
    const int col0 = blockIdx.x * 128;  // col n = g*H + h  (Wx row index)

    int rA[4], cA[4];
    long abase[4], bbase[4];
#pragma unroll
    for (int i = 0; i < 4; i++) {
        int s = tid + 256 * i;
        rA[i] = s >> 3;  // 0..127
        cA[i] = s & 7;   // float4 col 0..7 (BK=32)
        abase[i] = (long)(row0 + rA[i]) * (DD / 4) + cA[i];
        bbase[i] = (long)(col0 + rA[i]) * (DD / 4) + cA[i];
    }
    const float4* xg = (const float4*)x;
    const float4* wg = (const float4*)wx;

    float acc[4][4][4];
#pragma unroll
    for (int mi = 0; mi < 4; mi++)
#pragma unroll
        for (int ni = 0; ni < 4; ni++)
#pragma unroll
            for (int q = 0; q < 4; q++) acc[mi][ni][q] = 0.f;

    const int NSTAGE = DD / 32;  // 16
    float4 ra[4], rb[4];

    // prefetch + store stage 0
#pragma unroll
    for (int i = 0; i < 4; i++) { ra[i] = xg[abase[i]]; rb[i] = wg[bbase[i]]; }
#pragma unroll
    for (int i = 0; i < 4; i++) {
        float4 v = ra[i];
        v.x = to_tf32(v.x); v.y = to_tf32(v.y); v.z = to_tf32(v.z); v.w = to_tf32(v.w);
        *(float4*)&As[rA[i] * G1_LD + cA[i] * 4] = v;
        float4 u = rb[i];
        u.x = to_tf32(u.x); u.y = to_tf32(u.y); u.z = to_tf32(u.z); u.w = to_tf32(u.w);
        *(float4*)&Bs[rA[i] * G1_LD + cA[i] * 4] = u;
    }

    for (int s = 0; s < NSTAGE; s++) {
        __syncthreads();
        if (s + 1 < NSTAGE) {
#pragma unroll
            for (int i = 0; i < 4; i++) {
                ra[i] = xg[abase[i] + (long)(s + 1) * 8];
                rb[i] = wg[bbase[i] + (long)(s + 1) * 8];
            }
        }
        const float* Ab = As + (s & 1) * G1_AST;
        const float* Bb = Bs + (s & 1) * G1_AST;
#pragma unroll
        for (int kk = 0; kk < 4; kk++) {
            uint32_t af[4][4], bf[4][2];
            const int kb = kk * 8 + (l & 3);
#pragma unroll
            for (int mi = 0; mi < 4; mi++) {
                int m = wm * 64 + mi * 16 + (l >> 2);
                af[mi][0] = fasu(Ab[m * G1_LD + kb]);
                af[mi][1] = fasu(Ab[(m + 8) * G1_LD + kb]);
                af[mi][2] = fasu(Ab[m * G1_LD + kb + 4]);
                af[mi][3] = fasu(Ab[(m + 8) * G1_LD + kb + 4]);
            }
#pragma unroll
            for (int ni = 0; ni < 4; ni++) {
                int n = wn * 32 + ni * 8 + (l >> 2);
                bf[ni][0] = fasu(Bb[n * G1_LD + kb]);
                bf[ni][1] = fasu(Bb[n * G1_LD + kb + 4]);
            }
#pragma unroll
            for (int mi = 0; mi < 4; mi++)
#pragma unroll
                for (int ni = 0; ni < 4; ni++)
                    mma8(acc[mi][ni], af[mi], bf[ni]);
        }
        if (s + 1 < NSTAGE) {
            const int nb = (s + 1) & 1;
#pragma unroll
            for (int i = 0; i < 4; i++) {
                float4 v = ra[i];
                v.x = to_tf32(v.x); v.y = to_tf32(v.y); v.z = to_tf32(v.z); v.w = to_tf32(v.w);
                *(float4*)&As[nb * G1_AST + rA[i] * G1_LD + cA[i] * 4] = v;
                float4 u = rb[i];
                u.x = to_tf32(u.x); u.y = to_tf32(u.y); u.z = to_tf32(u.z); u.w = to_tf32(u.w);
                *(float4*)&Bs[nb * G1_AST + rA[i] * G1_LD + cA[i] * 4] = u;
            }
        }
    }

    // epilogue: scatter (b,t) row -> out row t*B+b, add bias
#pragma unroll
    for (int mi = 0; mi < 4; mi++) {
        int m = row0 + wm * 64 + mi * 16 + (l >> 2);
        long orow0 = (long)(m & 255) * BB + (m >> 8);
        int m2 = m + 8;  // stays within same b (tile rows < 128 from a 128-aligned base)
        long orow1 = (long)(m2 & 255) * BB + (m2 >> 8);
#pragma unroll
        for (int ni = 0; ni < 4; ni++) {
            int n = col0 + wn * 32 + ni * 8 + 2 * (l & 3);
            float bx = bias[n], by = bias[n + 1];
            *(float2*)&g_xproj[orow0 * NGC + n] =
                make_float2(acc[mi][ni][0] + bx, acc[mi][ni][1] + by);
            *(float2*)&g_xproj[orow1 * NGC + n] =
                make_float2(acc[mi][ni][2] + bx, acc[mi][ni][3] + by);
        }
    }
}

// ---------------- kernel 2: one LSTM timestep ----------------
// 128 CTAs; CTA j owns h-columns [8j, 8j+8). Tile: M=128 (batch) x N=32 (4 gates x 8 h),
// K=1024 (BK=64, 16 double-buffered stages). 8 warps as 4x2 (warp tile 32x16).
#define S_LD 68
#define S_AST (128 * S_LD)  // 8704 floats per A buffer
#define S_BST (32 * S_LD)   // 2176 floats per B buffer

__global__ void __launch_bounds__(256, 1)
lstm79_step(const float* __restrict__ wh, int t) {
    extern __shared__ float smem[];
    float* As = smem;               // [2][128][68]
    float* Bs = smem + 2 * S_AST;   // [2][32][68]

    const int tid = threadIdx.x;
    const int l = tid & 31;
    const int w = tid >> 5;
    const int wm = w >> 1;  // 0..3 : 32-row band
    const int wn = w & 1;   // 0..1 : 16-col band
    const int hbase = blockIdx.x * 8;

    const float* __restrict__ hin = g_h[t & 1];
    float* __restrict__ hout = g_h[(t + 1) & 1];

    // prefetch this CTA's xproj slice (consumed only in epilogue)
    float xp[4][4];
#pragma unroll
    for (int i = 0; i < 4; i++) {
        int e = tid + 256 * i;
        int b_ = e >> 3, hh = e & 7;
        long base = ((long)t * BB + b_) * NGC + hbase + hh;
#pragma unroll
        for (int g = 0; g < 4; g++) xp[i][g] = g_xproj[base + (long)g * HH];
    }

    // global load slots: A 2048 float4 (8/thread), B 512 float4 (2/thread)
    int rA[8], cA[8];
    long abase[8];
    const float4* hg = (const float4*)hin;
#pragma unroll
    for (int i = 0; i < 8; i++) {
        int s = tid + 256 * i;
        rA[i] = s >> 4;          // batch row 0..127
        cA[i] = s & 15;          // float4 col 0..15 (BK=64)
        abase[i] = (long)rA[i] * (HH / 4) + cA[i];
    }
    int rB[2], cB[2];
    long bbase[2];
    const float4* wg = (const float4*)wh;
#pragma unroll
    for (int i = 0; i < 2; i++) {
        int s = tid + 256 * i;
        int nl = s >> 4;  // 0..31: local col = gate*8 + hh
        cB[i] = s & 15;
        rB[i] = nl;
        long whrow = (long)(nl >> 3) * HH + hbase + (nl & 7);
        bbase[i] = whrow * (HH / 4) + cB[i];
    }

    float acc[2][2][4];
#pragma unroll
    for (int mi = 0; mi < 2; mi++)
#pragma unroll
        for (int ni = 0; ni < 2; ni++)
#pragma unroll
            for (int q = 0; q < 4; q++) acc[mi][ni][q] = 0.f;

    const int NSTAGE = HH / 64;  // 16
    float4 ra[8], rb[2];

#pragma unroll
    for (int i = 0; i < 8; i++) ra[i] = hg[abase[i]];
#pragma unroll
    for (int i = 0; i < 2; i++) rb[i] = wg[bbase[i]];
#pragma unroll
    for (int i = 0; i < 8; i++) {
        float4 v = ra[i];
        v.x = to_tf32(v.x); v.y = to_tf32(v.y); v.z = to_tf32(v.z); v.w = to_tf32(v.w);
        *(float4*)&As[rA[i] * S_LD + cA[i] * 4] = v;
    }
#pragma unroll
    for (int i = 0; i < 2; i++) {
        float4 u = rb[i];
        u.x = to_tf32(u.x); u.y = to_tf32(u.y); u.z = to_tf32(u.z); u.w = to_tf32(u.w);
        *(float4*)&Bs[rB[i] * S_LD + cB[i] * 4] = u;
    }

    for (int s = 0; s < NSTAGE; s++) {
        __syncthreads();
        if (s + 1 < NSTAGE) {
#pragma unroll
            for (int i = 0; i < 8; i++) ra[i] = hg[abase[i] + (long)(s + 1) * 16];
#pragma unroll
            for (int i = 0; i < 2; i++) rb[i] = wg[bbase[i] + (long)(s + 1) * 16];
        }
        const float* Ab = As + (s & 1) * S_AST;
        const float* Bb = Bs + (s & 1) * S_BST;
#pragma unroll
        for (int kk = 0; kk < 8; kk++) {
            uint32_t af[2][4], bf[2][2];
            const int kb = kk * 8 + (l & 3);
#pragma unroll
            for (int mi = 0; mi < 2; mi++) {
                int m = wm * 32 + mi * 16 + (l >> 2);
                af[mi][0] = fasu(Ab[m * S_LD + kb]);
                af[mi][1] = fasu(Ab[(m + 8) * S_LD + kb]);
                af[mi][2] = fasu(Ab[m * S_LD + kb + 4]);
                af[mi][3] = fasu(Ab[(m + 8) * S_LD + kb + 4]);
            }
#pragma unroll
            for (int ni = 0; ni < 2; ni++) {
                int n = wn * 16 + ni * 8 + (l >> 2);
                bf[ni][0] = fasu(Bb[n * S_LD + kb]);
                bf[ni][1] = fasu(Bb[n * S_LD + kb + 4]);
            }
#pragma unroll
            for (int mi = 0; mi < 2; mi++)
#pragma unroll
                for (int ni = 0; ni < 2; ni++)
                    mma8(acc[mi][ni], af[mi], bf[ni]);
        }
        if (s + 1 < NSTAGE) {
            const int nb = (s + 1) & 1;
#pragma unroll
            for (int i = 0; i < 8; i++) {
                float4 v = ra[i];
                v.x = to_tf32(v.x); v.y = to_tf32(v.y); v.z = to_tf32(v.z); v.w = to_tf32(v.w);
                *(float4*)&As[nb * S_AST + rA[i] * S_LD + cA[i] * 4] = v;
            }
#pragma unroll
            for (int i = 0; i < 2; i++) {
                float4 u = rb[i];
                u.x = to_tf32(u.x); u.y = to_tf32(u.y); u.z = to_tf32(u.z); u.w = to_tf32(u.w);
                *(float4*)&Bs[nb * S_BST + rB[i] * S_LD + cB[i] * 4] = u;
            }
        }
    }

    // epilogue: gate tile -> smem, LSTM pointwise update
    __syncthreads();
    float* sg = smem;  // [128][36]
#pragma unroll
    for (int mi = 0; mi < 2; mi++) {
        int m = wm * 32 + mi * 16 + (l >> 2);
#pragma unroll
        for (int ni = 0; ni < 2; ni++) {
            int n = wn * 16 + ni * 8 + 2 * (l & 3);
            *(float2*)&sg[m * 36 + n] = make_float2(acc[mi][ni][0], acc[mi][ni][1]);
            *(float2*)&sg[(m + 8) * 36 + n] = make_float2(acc[mi][ni][2], acc[mi][ni][3]);
        }
    }
    __syncthreads();
#pragma unroll
    for (int i = 0; i < 4; i++) {
        int e = tid + 256 * i;
        int b_ = e >> 3, hh = e & 7;
        const float* gr = &sg[b_ * 36];
        float zi = gr[hh] + xp[i][0];
        float zf = gr[8 + hh] + xp[i][1];
        float zg = gr[16 + hh] + xp[i][2];
        float zo = gr[24 + hh] + xp[i][3];
        float si = sigm(zi), sf = sigm(zf), tg = tanhx(zg), so = sigm(zo);
        int ci = b_ * HH + hbase + hh;
        float cn = sf * g_c[ci] + si * tg;
        g_c[ci] = cn;
        hout[ci] = so * tanhx(cn);
    }
}

// ---------------- kernel 3: logits + softmax ----------------
__global__ void __launch_bounds__(256, 1)
lstm79_final(const float* __restrict__ whp, const float* __restrict__ bhp,
             float* __restrict__ out) {
    __shared__ float sh[HH];
    __shared__ float red[8];
    const int b_ = blockIdx.x;
    const int tid = threadIdx.x;
    const float* hrow = g_h[0] + (long)b_ * HH;  // after 256 steps state lives in buf 0
    for (int k = tid; k < HH; k += 256) sh[k] = hrow[k];
    __syncthreads();

    float lg[4];
#pragma unroll
    for (int j = 0; j < 4; j++) {
        int o = tid + j * 256;
        const float4* wp = (const float4*)(whp + (long)o * HH);
        const float4* hp = (const float4*)sh;
        float d0 = 0.f, d1 = 0.f, d2 = 0.f, d3 = 0.f;
#pragma unroll 8
        for (int k = 0; k < HH / 4; k++) {
            float4 wv = wp[k];
            float4 hv = hp[k];
            d0 += wv.x * hv.x; d1 += wv.y * hv.y;
            d2 += wv.z * hv.z; d3 += wv.w * hv.w;
        }
        lg[j] = (d0 + d1) + (d2 + d3) + bhp[o];
    }
    float mx = fmaxf(fmaxf(lg[0], lg[1]), fmaxf(lg[2], lg[3]));
#pragma unroll
    for (int o = 16; o; o >>= 1) mx = fmaxf(mx, __shfl_xor_sync(0xffffffffu, mx, o));
    if (!(tid & 31)) red[tid >> 5] = mx;
    __syncthreads();
    mx = red[0];
#pragma unroll
    for (int i = 1; i < 8; i++) mx = fmaxf(mx, red[i]);
    __syncthreads();
    float ex[4];
    float se = 0.f;
#pragma unroll
    for (int j = 0; j < 4; j++) { ex[j] = __expf(lg[j] - mx); se += ex[j]; }
#pragma unroll
    for (int o = 16; o; o >>= 1) se += __shfl_xor_sync(0xffffffffu, se, o);
    if (!(tid & 31)) red[tid >> 5] = se;
    __syncthreads();
    se = 0.f;
#pragma unroll
    for (int i = 0; i < 8; i++) se += red[i];
    float inv = 1.f / se;
#pragma unroll
    for (int j = 0; j < 4; j++) out[(long)b_ * OO + tid + j * 256] = ex[j] * inv;
}

// ---------------- host launcher ----------------
extern "C" void kernel_launch(void* const* d_in, const int* in_sizes, int n_in,
                              void* d_out, int out_size) {
    (void)in_sizes; (void)n_in; (void)out_size;
    const float* x   = (const float*)d_in[0];
    const float* Wx  = (const float*)d_in[1];
    const float* Wh  = (const float*)d_in[2];
    const float* bb  = (const float*)d_in[3];
    const float* Whp = (const float*)d_in[4];
    const float* bhp = (const float*)d_in[5];
    float* out = (float*)d_out;

    const int smem1 = (2 * G1_AST + 2 * G1_AST) * (int)sizeof(float);  // 73728
    const int smem2 = (2 * S_AST + 2 * S_BST) * (int)sizeof(float);    // 87040
    cudaFuncSetAttribute(lstm79_xproj, cudaFuncAttributeMaxDynamicSharedMemorySize, smem1);
    cudaFuncSetAttribute(lstm79_step, cudaFuncAttributeMaxDynamicSharedMemorySize, smem2);

    lstm79_init<<<512, 256>>>();
    lstm79_xproj<<<dim3(32, 256), 256, smem1>>>(x, Wx, bb);
    for (int t = 0; t < TT; t++)
        lstm79_step<<<128, 256, smem2>>>(Wh, t);
    lstm79_final<<<BB, 256>>>(Whp, bhp, out);
}

// round 11
// speedup vs baseline: 1.0393x; 1.0393x over previous
#include <cuda_runtime.h>
#include <cstdint>

#define BB 128
#define TT 256
#define DD 512
#define HH 1024
#define OO 1024
#define NGC 4096  // 4*H

// ---------------- device scratch (allocation-free contract) ----------------
__device__ float g_xproj[(size_t)TT * BB * NGC];  // [t][b][4H], 512 MB
__device__ float g_h[2][BB * HH];                 // ping-pong hidden state
__device__ unsigned int g_count;                  // grid barrier arrive counter
__device__ unsigned int g_sense;                  // grid barrier generation

// ---------------- helpers ----------------
__device__ __forceinline__ float to_tf32(float x) {
    uint32_t u;
    asm("cvt.rna.tf32.f32 %0, %1;" : "=r"(u) : "f"(x));
    return __uint_as_float(u);
}
__device__ __forceinline__ uint32_t fasu(float x) { return __float_as_uint(x); }

__device__ __forceinline__ void mma8(float* c, const uint32_t* a, const uint32_t* b) {
    asm volatile(
        "mma.sync.aligned.m16n8k8.row.col.f32.tf32.tf32.f32 "
        "{%0,%1,%2,%3}, {%4,%5,%6,%7}, {%8,%9}, {%0,%1,%2,%3};\n"
        : "+f"(c[0]), "+f"(c[1]), "+f"(c[2]), "+f"(c[3])
        : "r"(a[0]), "r"(a[1]), "r"(a[2]), "r"(a[3]), "r"(b[0]), "r"(b[1]));
}

__device__ __forceinline__ float sigm(float x) { return 1.f / (1.f + __expf(-x)); }
__device__ __forceinline__ float tanhx(float x) { return 1.f - 2.f / (1.f + __expf(2.f * x)); }

// ---------------- init: zero h0 and barrier state ----------------
__global__ void lstm79_init() {
    int i = blockIdx.x * blockDim.x + threadIdx.x;  // grid 512*256 = BB*HH exactly
    g_h[0][i] = 0.f;
    if (i == 0) { g_count = 0u; g_sense = 0u; }
}

// ---------------- kernel 1: xproj = x @ Wx^T + b, scattered to [t][b][4H] ----
#define G1_LD 36                 // padded smem row stride (floats)
#define G1_AST (128 * G1_LD)

__global__ void __launch_bounds__(256, 1)
lstm79_xproj(const float* __restrict__ x, const float* __restrict__ wx,
             const float* __restrict__ bias) {
    extern __shared__ float smem[];
    float* As = smem;               // [2][128][36]
    float* Bs = smem + 2 * G1_AST;  // [2][128][36]

    const int tid = threadIdx.x;
    const int l = tid & 31;
    const int w = tid >> 5;
    const int wm = w >> 2;  // 0..1 : 64-row warp band
    const int wn = w & 3;   // 0..3 : 32-col warp band
    const int row0 = blockIdx.y * 128;  // row r = b*T + t  (x layout)
    const int col0 = blockIdx.x * 128;  // col n = g*H + h  (Wx row index)

    int rA[4], cA[4];
    long abase[4], bbase[4];
#pragma unroll
    for (int i = 0; i < 4; i++) {
        int s = tid + 256 * i;
        rA[i] = s >> 3;  // 0..127
        cA[i] = s & 7;   // float4 col 0..7 (BK=32)
        abase[i] = (long)(row0 + rA[i]) * (DD / 4) + cA[i];
        bbase[i] = (long)(col0 + rA[i]) * (DD / 4) + cA[i];
    }
    const float4* xg = (const float4*)x;
    const float4* wg = (const float4*)wx;

    float acc[4][4][4];
#pragma unroll
    for (int mi = 0; mi < 4; mi++)
#pragma unroll
        for (int ni = 0; ni < 4; ni++)
#pragma unroll
            for (int q = 0; q < 4; q++) acc[mi][ni][q] = 0.f;

    const int NSTAGE = DD / 32;  // 16
    float4 ra[4], rb[4];

#pragma unroll
    for (int i = 0; i < 4; i++) { ra[i] = xg[abase[i]]; rb[i] = wg[bbase[i]]; }
#pragma unroll
    for (int i = 0; i < 4; i++) {
        float4 v = ra[i];
        v.x = to_tf32(v.x); v.y = to_tf32(v.y); v.z = to_tf32(v.z); v.w = to_tf32(v.w);
        *(float4*)&As[rA[i] * G1_LD + cA[i] * 4] = v;
        float4 u = rb[i];
        u.x = to_tf32(u.x); u.y = to_tf32(u.y); u.z = to_tf32(u.z); u.w = to_tf32(u.w);
        *(float4*)&Bs[rA[i] * G1_LD + cA[i] * 4] = u;
    }

    for (int s = 0; s < NSTAGE; s++) {
        __syncthreads();
        if (s + 1 < NSTAGE) {
#pragma unroll
            for (int i = 0; i < 4; i++) {
                ra[i] = xg[abase[i] + (long)(s + 1) * 8];
                rb[i] = wg[bbase[i] + (long)(s + 1) * 8];
            }
        }
        const float* Ab = As + (s & 1) * G1_AST;
        const float* Bb = Bs + (s & 1) * G1_AST;
#pragma unroll
        for (int kk = 0; kk < 4; kk++) {
            uint32_t af[4][4], bf[4][2];
            const int kb = kk * 8 + (l & 3);
#pragma unroll
            for (int mi = 0; mi < 4; mi++) {
                int m = wm * 64 + mi * 16 + (l >> 2);
                af[mi][0] = fasu(Ab[m * G1_LD + kb]);
                af[mi][1] = fasu(Ab[(m + 8) * G1_LD + kb]);
                af[mi][2] = fasu(Ab[m * G1_LD + kb + 4]);
                af[mi][3] = fasu(Ab[(m + 8) * G1_LD + kb + 4]);
            }
#pragma unroll
            for (int ni = 0; ni < 4; ni++) {
                int n = wn * 32 + ni * 8 + (l >> 2);
                bf[ni][0] = fasu(Bb[n * G1_LD + kb]);
                bf[ni][1] = fasu(Bb[n * G1_LD + kb + 4]);
            }
#pragma unroll
            for (int mi = 0; mi < 4; mi++)
#pragma unroll
                for (int ni = 0; ni < 4; ni++)
                    mma8(acc[mi][ni], af[mi], bf[ni]);
        }
        if (s + 1 < NSTAGE) {
            const int nb = (s + 1) & 1;
#pragma unroll
            for (int i = 0; i < 4; i++) {
                float4 v = ra[i];
                v.x = to_tf32(v.x); v.y = to_tf32(v.y); v.z = to_tf32(v.z); v.w = to_tf32(v.w);
                *(float4*)&As[nb * G1_AST + rA[i] * G1_LD + cA[i] * 4] = v;
                float4 u = rb[i];
                u.x = to_tf32(u.x); u.y = to_tf32(u.y); u.z = to_tf32(u.z); u.w = to_tf32(u.w);
                *(float4*)&Bs[nb * G1_AST + rA[i] * G1_LD + cA[i] * 4] = u;
            }
        }
    }

    // epilogue: scatter (b,t) row -> out row t*B+b, add bias
#pragma unroll
    for (int mi = 0; mi < 4; mi++) {
        int m = row0 + wm * 64 + mi * 16 + (l >> 2);
        long orow0 = (long)(m & 255) * BB + (m >> 8);
        int m2 = m + 8;
        long orow1 = (long)(m2 & 255) * BB + (m2 >> 8);
#pragma unroll
        for (int ni = 0; ni < 4; ni++) {
            int n = col0 + wn * 32 + ni * 8 + 2 * (l & 3);
            float bx = bias[n], by = bias[n + 1];
            *(float2*)&g_xproj[orow0 * NGC + n] =
                make_float2(acc[mi][ni][0] + bx, acc[mi][ni][1] + by);
            *(float2*)&g_xproj[orow1 * NGC + n] =
                make_float2(acc[mi][ni][2] + bx, acc[mi][ni][3] + by);
        }
    }
}

// ---------------- kernel 2: PERSISTENT recurrence, all 256 steps ----------------
// 128 CTAs, 1/SM. CTA j owns h-cols [8j,8j+8) -> N=32 gate cols (4 gates x 8 h).
// Wh slice [32][1024] lives in SMEM (tf32) for the whole kernel (131.6 KB).
// Split-K: warps 0-3 do K[0:512], warps 4-7 do K[512:1024]; each warp tile 32x32.
// A (h) streamed global->smem, BK=32, double buffered: [2][2grp][128][36].
// Cell state c lives in registers (4/thread) for all 256 steps.
#define P_BS_LD 1028            // Wh smem row stride (== 4 mod 32 -> conflict-free)
#define P_B_FLOATS (32 * P_BS_LD)
#define P_GST (128 * 36)        // one K-group A plane
#define P_AST (2 * P_GST)       // one double-buffer stage (both groups)

__global__ void __launch_bounds__(256, 1)
lstm79_run(const float* __restrict__ wh) {
    extern __shared__ float smem[];
    float* Bs = smem;                  // [32][1028] persistent Wh slice
    float* As = smem + P_B_FLOATS;     // [2][2][128][36]
    float* sg = As;                    // epilogue gate buffer aliases A buf0/grp0

    const int tid = threadIdx.x;
    const int l = tid & 31;
    const int w = tid >> 5;
    const int grp = w >> 2;   // K-half
    const int wrow = w & 3;   // 32-row band
    const int hbase = blockIdx.x * 8;

    // ---- load Wh slice into smem (tf32), once per launch ----
    {
        const float4* wg = (const float4*)wh;
        for (int idx = tid; idx < 32 * 256; idx += 256) {
            int n = idx >> 8;     // 0..31 : gate*8 + hcol
            int c4 = idx & 255;
            long grow = (long)(n >> 3) * HH + hbase + (n & 7);
            float4 u = wg[grow * (HH / 4) + c4];
            u.x = to_tf32(u.x); u.y = to_tf32(u.y); u.z = to_tf32(u.z); u.w = to_tf32(u.w);
            *(float4*)&Bs[n * P_BS_LD + c4 * 4] = u;
        }
    }
    __syncthreads();

    // A global/smem slot mapping: 8 float4 per thread per stage
    long abase[8];
    int soff[8];
#pragma unroll
    for (int i = 0; i < 8; i++) {
        int s = tid + 256 * i;
        int g = s >> 10;            // K-group plane
        int r = (s >> 3) & 127;     // batch row
        int c4 = s & 7;             // float4 col within BK=32
        abase[i] = (long)r * (HH / 4) + g * 128 + c4;
        soff[i] = g * P_GST + r * 36 + c4 * 4;
    }

    // pointwise element mapping (4 per thread, fixed for whole kernel)
    int eb[4], ehh[4];
#pragma unroll
    for (int i = 0; i < 4; i++) { int e = tid + 256 * i; eb[i] = e >> 3; ehh[i] = e & 7; }

    float cst[4] = {0.f, 0.f, 0.f, 0.f};  // cell state in registers

    for (int t = 0; t < TT; t++) {
        const float* __restrict__ hin = g_h[t & 1];
        float* __restrict__ hout = g_h[(t + 1) & 1];
        const float4* hg = (const float4*)hin;

        // prefetch this step's xproj slice (consumed in pointwise phase)
        float xp[4][4];
#pragma unroll
        for (int i = 0; i < 4; i++) {
            long base = ((long)t * BB + eb[i]) * NGC + hbase + ehh[i];
#pragma unroll
            for (int g = 0; g < 4; g++) xp[i][g] = __ldcg(&g_xproj[base + (long)g * HH]);
        }

        float acc[2][4][4];
#pragma unroll
        for (int mi = 0; mi < 2; mi++)
#pragma unroll
            for (int ni = 0; ni < 4; ni++)
#pragma unroll
                for (int q = 0; q < 4; q++) acc[mi][ni][q] = 0.f;

        float4 ra[8];
#pragma unroll
        for (int i = 0; i < 8; i++) ra[i] = __ldcg(&hg[abase[i]]);
#pragma unroll
        for (int i = 0; i < 8; i++) {
            float4 v = ra[i];
            v.x = to_tf32(v.x); v.y = to_tf32(v.y); v.z = to_tf32(v.z); v.w = to_tf32(v.w);
            *(float4*)&As[soff[i]] = v;
        }

        const int NSTAGE = 16;  // 512 / 32 per K-group
        for (int s = 0; s < NSTAGE; s++) {
            __syncthreads();
            if (s + 1 < NSTAGE) {
#pragma unroll
                for (int i = 0; i < 8; i++) ra[i] = __ldcg(&hg[abase[i] + (long)(s + 1) * 8]);
            }
            const float* Ab = As + (s & 1) * P_AST + grp * P_GST;
            const int koff = grp * 512 + s * 32;
#pragma unroll
            for (int kk = 0; kk < 4; kk++) {
                uint32_t af[2][4], bf[4][2];
                const int kb = kk * 8 + (l & 3);
#pragma unroll
                for (int mi = 0; mi < 2; mi++) {
                    int m = wrow * 32 + mi * 16 + (l >> 2);
                    af[mi][0] = fasu(Ab[m * 36 + kb]);
                    af[mi][1] = fasu(Ab[(m + 8) * 36 + kb]);
                    af[mi][2] = fasu(Ab[m * 36 + kb + 4]);
                    af[mi][3] = fasu(Ab[(m + 8) * 36 + kb + 4]);
                }
#pragma unroll
                for (int ni = 0; ni < 4; ni++) {
                    int n = ni * 8 + (l >> 2);
                    bf[ni][0] = fasu(Bs[n * P_BS_LD + koff + kb]);
                    bf[ni][1] = fasu(Bs[n * P_BS_LD + koff + kb + 4]);
                }
#pragma unroll
                for (int mi = 0; mi < 2; mi++)
#pragma unroll
                    for (int ni = 0; ni < 4; ni++)
                        mma8(acc[mi][ni], af[mi], bf[ni]);
            }
            if (s + 1 < NSTAGE) {
                const int nb = (s + 1) & 1;
#pragma unroll
                for (int i = 0; i < 8; i++) {
                    float4 v = ra[i];
                    v.x = to_tf32(v.x); v.y = to_tf32(v.y); v.z = to_tf32(v.z); v.w = to_tf32(v.w);
                    *(float4*)&As[nb * P_AST + soff[i]] = v;
                }
            }
        }

        // ---- epilogue: cross-group reduction in smem (sg aliases A buf0) ----
        if (grp == 0) {
#pragma unroll
            for (int mi = 0; mi < 2; mi++) {
                int m = wrow * 32 + mi * 16 + (l >> 2);
#pragma unroll
                for (int ni = 0; ni < 4; ni++) {
                    int n = ni * 8 + 2 * (l & 3);
                    *(float2*)&sg[m * 36 + n] = make_float2(acc[mi][ni][0], acc[mi][ni][1]);
                    *(float2*)&sg[(m + 8) * 36 + n] = make_float2(acc[mi][ni][2], acc[mi][ni][3]);
                }
            }
        }
        __syncthreads();
        if (grp == 1) {
#pragma unroll
            for (int mi = 0; mi < 2; mi++) {
                int m = wrow * 32 + mi * 16 + (l >> 2);
#pragma unroll
                for (int ni = 0; ni < 4; ni++) {
                    int n = ni * 8 + 2 * (l & 3);
                    float2* p0 = (float2*)&sg[m * 36 + n];
                    float2 v0 = *p0; v0.x += acc[mi][ni][0]; v0.y += acc[mi][ni][1]; *p0 = v0;
                    float2* p1 = (float2*)&sg[(m + 8) * 36 + n];
                    float2 v1 = *p1; v1.x += acc[mi][ni][2]; v1.y += acc[mi][ni][3]; *p1 = v1;
                }
            }
        }
        __syncthreads();

        // ---- LSTM pointwise update (c in registers) ----
#pragma unroll
        for (int i = 0; i < 4; i++) {
            const float* gr = &sg[eb[i] * 36];
            float zi = gr[ehh[i]] + xp[i][0];
            float zf = gr[8 + ehh[i]] + xp[i][1];
            float zg = gr[16 + ehh[i]] + xp[i][2];
            float zo = gr[24 + ehh[i]] + xp[i][3];
            float si = sigm(zi), sf = sigm(zf), tg = tanhx(zg), so = sigm(zo);
            float cn = sf * cst[i] + si * tg;
            cst[i] = cn;
            hout[eb[i] * HH + hbase + ehh[i]] = so * tanhx(cn);
        }

        // ---- grid-wide barrier (sense/generation) ----
        __threadfence();   // release our hout writes to L2
        __syncthreads();
        if (tid == 0) {
            unsigned int arr = atomicAdd(&g_count, 1u);
            if (arr == (unsigned int)(gridDim.x - 1)) {
                g_count = 0u;
                __threadfence();
                *(volatile unsigned int*)&g_sense = (unsigned int)(t + 1);
            } else {
                while (*(volatile unsigned int*)&g_sense < (unsigned int)(t + 1)) {}
            }
        }
        __syncthreads();
        __threadfence();   // gpu-scope fence: invalidate L1 so next-step h reads are fresh
    }
}

// ---------------- kernel 3: logits + softmax ----------------
__global__ void __launch_bounds__(256, 1)
lstm79_final(const float* __restrict__ whp, const float* __restrict__ bhp,
             float* __restrict__ out) {
    __shared__ float sh[HH];
    __shared__ float red[8];
    const int b_ = blockIdx.x;
    const int tid = threadIdx.x;
    const float* hrow = g_h[0] + (long)b_ * HH;  // after 256 steps state lives in buf 0
    for (int k = tid; k < HH; k += 256) sh[k] = hrow[k];
    __syncthreads();

    float lg[4];
#pragma unroll
    for (int j = 0; j < 4; j++) {
        int o = tid + j * 256;
        const float4* wp = (const float4*)(whp + (long)o * HH);
        const float4* hp = (const float4*)sh;
        float d0 = 0.f, d1 = 0.f, d2 = 0.f, d3 = 0.f;
#pragma unroll 8
        for (int k = 0; k < HH / 4; k++) {
            float4 wv = wp[k];
            float4 hv = hp[k];
            d0 += wv.x * hv.x; d1 += wv.y * hv.y;
            d2 += wv.z * hv.z; d3 += wv.w * hv.w;
        }
        lg[j] = (d0 + d1) + (d2 + d3) + bhp[o];
    }
    float mx = fmaxf(fmaxf(lg[0], lg[1]), fmaxf(lg[2], lg[3]));
#pragma unroll
    for (int o = 16; o; o >>= 1) mx = fmaxf(mx, __shfl_xor_sync(0xffffffffu, mx, o));
    if (!(tid & 31)) red[tid >> 5] = mx;
    __syncthreads();
    mx = red[0];
#pragma unroll
    for (int i = 1; i < 8; i++) mx = fmaxf(mx, red[i]);
    __syncthreads();
    float ex[4];
    float se = 0.f;
#pragma unroll
    for (int j = 0; j < 4; j++) { ex[j] = __expf(lg[j] - mx); se += ex[j]; }
#pragma unroll
    for (int o = 16; o; o >>= 1) se += __shfl_xor_sync(0xffffffffu, se, o);
    if (!(tid & 31)) red[tid >> 5] = se;
    __syncthreads();
    se = 0.f;
#pragma unroll
    for (int i = 0; i < 8; i++) se += red[i];
    float inv = 1.f / se;
#pragma unroll
    for (int j = 0; j < 4; j++) out[(long)b_ * OO + tid + j * 256] = ex[j] * inv;
}

// ---------------- host launcher ----------------
extern "C" void kernel_launch(void* const* d_in, const int* in_sizes, int n_in,
                              void* d_out, int out_size) {
    (void)in_sizes; (void)n_in; (void)out_size;
    const float* x   = (const float*)d_in[0];
    const float* Wx  = (const float*)d_in[1];
    const float* Wh  = (const float*)d_in[2];
    const float* bb  = (const float*)d_in[3];
    const float* Whp = (const float*)d_in[4];
    const float* bhp = (const float*)d_in[5];
    float* out = (float*)d_out;

    const int smem1 = (4 * G1_AST) * (int)sizeof(float);               // 73728
    const int smemP = (P_B_FLOATS + 2 * P_AST) * (int)sizeof(float);   // 205312
    cudaFuncSetAttribute(lstm79_xproj, cudaFuncAttributeMaxDynamicSharedMemorySize, smem1);
    cudaFuncSetAttribute(lstm79_run, cudaFuncAttributeMaxDynamicSharedMemorySize, smemP);

    lstm79_init<<<512, 256>>>();
    lstm79_xproj<<<dim3(32, 256), 256, smem1>>>(x, Wx, bb);
    lstm79_run<<<128, 256, smemP>>>(Wh);
    lstm79_final<<<BB, 256>>>(Whp, bhp, out);
}

// round 13
// speedup vs baseline: 1.2302x; 1.1837x over previous
#include <cuda_runtime.h>
#include <cstdint>

#define BB 128
#define TT 256
#define DD 512
#define HH 1024
#define OO 1024
#define NGC 4096  // 4*H

// ---------------- device scratch (allocation-free contract) ----------------
__device__ float g_xproj[(size_t)TT * BB * NGC];  // [t][b][4H], 512 MB
__device__ float g_h[2][BB * HH];                 // ping-pong hidden state
__device__ float g_logits[BB * OO];               // pre-softmax logits
__device__ unsigned int g_count;                  // grid barrier arrive counter
__device__ unsigned int g_sense;                  // grid barrier generation

// ---------------- helpers ----------------
__device__ __forceinline__ float to_tf32(float x) {
    uint32_t u;
    asm("cvt.rna.tf32.f32 %0, %1;" : "=r"(u) : "f"(x));
    return __uint_as_float(u);
}
__device__ __forceinline__ uint32_t fasu(float x) { return __float_as_uint(x); }

__device__ __forceinline__ void mma8(float* c, const uint32_t* a, const uint32_t* b) {
    asm volatile(
        "mma.sync.aligned.m16n8k8.row.col.f32.tf32.tf32.f32 "
        "{%0,%1,%2,%3}, {%4,%5,%6,%7}, {%8,%9}, {%0,%1,%2,%3};\n"
        : "+f"(c[0]), "+f"(c[1]), "+f"(c[2]), "+f"(c[3])
        : "r"(a[0]), "r"(a[1]), "r"(a[2]), "r"(a[3]), "r"(b[0]), "r"(b[1]));
}

__device__ __forceinline__ void cp16(uint32_t saddr, const void* gaddr) {
    asm volatile("cp.async.cg.shared.global [%0], [%1], 16;\n" :: "r"(saddr), "l"(gaddr));
}
__device__ __forceinline__ void cp_commit() {
    asm volatile("cp.async.commit_group;\n" ::: "memory");
}
__device__ __forceinline__ void cp_wait0() {
    asm volatile("cp.async.wait_group 0;\n" ::: "memory");
}

__device__ __forceinline__ float sigm(float x) { return 1.f / (1.f + __expf(-x)); }
__device__ __forceinline__ float tanhx(float x) { return 1.f - 2.f / (1.f + __expf(2.f * x)); }

// ---------------- init: zero h0 and barrier state ----------------
__global__ void lstm79_init() {
    int i = blockIdx.x * blockDim.x + threadIdx.x;  // grid 512*256 = BB*HH exactly
    g_h[0][i] = 0.f;
    if (i == 0) { g_count = 0u; g_sense = 0u; }
}

// ---------------- kernel 1: xproj = x @ Wx^T + b, scattered to [t][b][4H] ----
#define G1_LD 36                 // padded smem row stride (floats)
#define G1_AST (128 * G1_LD)

__global__ void __launch_bounds__(256, 1)
lstm79_xproj(const float* __restrict__ x, const float* __restrict__ wx,
             const float* __restrict__ bias) {
    extern __shared__ float smem[];
    float* As = smem;               // [2][128][36]
    float* Bs = smem + 2 * G1_AST;  // [2][128][36]

    const int tid = threadIdx.x;
    const int l = tid & 31;
    const int w = tid >> 5;
    const int wm = w >> 2;  // 0..1 : 64-row warp band
    const int wn = w & 3;   // 0..3 : 32-col warp band
    const int row0 = blockIdx.y * 128;  // row r = b*T + t  (x layout)
    const int col0 = blockIdx.x * 128;  // col n = g*H + h  (Wx row index)

    int rA[4], cA[4];
    long abase[4], bbase[4];
#pragma unroll
    for (int i = 0; i < 4; i++) {
        int s = tid + 256 * i;
        rA[i] = s >> 3;  // 0..127
        cA[i] = s & 7;   // float4 col 0..7 (BK=32)
        abase[i] = (long)(row0 + rA[i]) * (DD / 4) + cA[i];
        bbase[i] = (long)(col0 + rA[i]) * (DD / 4) + cA[i];
    }
    const float4* xg = (const float4*)x;
    const float4* wg = (const float4*)wx;

    float acc[4][4][4];
#pragma unroll
    for (int mi = 0; mi < 4; mi++)
#pragma unroll
        for (int ni = 0; ni < 4; ni++)
#pragma unroll
            for (int q = 0; q < 4; q++) acc[mi][ni][q] = 0.f;

    const int NSTAGE = DD / 32;  // 16
    float4 ra[4], rb[4];

#pragma unroll
    for (int i = 0; i < 4; i++) { ra[i] = xg[abase[i]]; rb[i] = wg[bbase[i]]; }
#pragma unroll
    for (int i = 0; i < 4; i++) {
        float4 v = ra[i];
        v.x = to_tf32(v.x); v.y = to_tf32(v.y); v.z = to_tf32(v.z); v.w = to_tf32(v.w);
        *(float4*)&As[rA[i] * G1_LD + cA[i] * 4] = v;
        float4 u = rb[i];
        u.x = to_tf32(u.x); u.y = to_tf32(u.y); u.z = to_tf32(u.z); u.w = to_tf32(u.w);
        *(float4*)&Bs[rA[i] * G1_LD + cA[i] * 4] = u;
    }

    // fragment base offsets (constant per thread)
    const int aoff = (wm * 64 + (l >> 2)) * G1_LD + (l & 3);
    const int boff = (wn * 32 + (l >> 2)) * G1_LD + (l & 3);

    for (int s = 0; s < NSTAGE; s++) {
        __syncthreads();
        if (s + 1 < NSTAGE) {
#pragma unroll
            for (int i = 0; i < 4; i++) {
                ra[i] = xg[abase[i] + (long)(s + 1) * 8];
                rb[i] = wg[bbase[i] + (long)(s + 1) * 8];
            }
        }
        const float* pA = As + (s & 1) * G1_AST + aoff;
        const float* pB = Bs + (s & 1) * G1_AST + boff;
#pragma unroll
        for (int kk = 0; kk < 4; kk++) {
            uint32_t af[4][4], bf[4][2];
            const int ko = kk * 8;
#pragma unroll
            for (int mi = 0; mi < 4; mi++) {
                af[mi][0] = fasu(pA[mi * 576 + ko]);
                af[mi][1] = fasu(pA[mi * 576 + 288 + ko]);
                af[mi][2] = fasu(pA[mi * 576 + ko + 4]);
                af[mi][3] = fasu(pA[mi * 576 + 288 + ko + 4]);
            }
#pragma unroll
            for (int ni = 0; ni < 4; ni++) {
                bf[ni][0] = fasu(pB[ni * 288 + ko]);
                bf[ni][1] = fasu(pB[ni * 288 + ko + 4]);
            }
#pragma unroll
            for (int mi = 0; mi < 4; mi++)
#pragma unroll
                for (int ni = 0; ni < 4; ni++)
                    mma8(acc[mi][ni], af[mi], bf[ni]);
        }
        if (s + 1 < NSTAGE) {
            const int nb = (s + 1) & 1;
#pragma unroll
            for (int i = 0; i < 4; i++) {
                float4 v = ra[i];
                v.x = to_tf32(v.x); v.y = to_tf32(v.y); v.z = to_tf32(v.z); v.w = to_tf32(v.w);
                *(float4*)&As[nb * G1_AST + rA[i] * G1_LD + cA[i] * 4] = v;
                float4 u = rb[i];
                u.x = to_tf32(u.x); u.y = to_tf32(u.y); u.z = to_tf32(u.z); u.w = to_tf32(u.w);
                *(float4*)&Bs[nb * G1_AST + rA[i] * G1_LD + cA[i] * 4] = u;
            }
        }
    }

    // epilogue: scatter (b,t) row -> out row t*B+b, add bias
#pragma unroll
    for (int mi = 0; mi < 4; mi++) {
        int m = row0 + wm * 64 + mi * 16 + (l >> 2);
        long orow0 = (long)(m & 255) * BB + (m >> 8);
        int m2 = m + 8;
        long orow1 = (long)(m2 & 255) * BB + (m2 >> 8);
#pragma unroll
        for (int ni = 0; ni < 4; ni++) {
            int n = col0 + wn * 32 + ni * 8 + 2 * (l & 3);
            float bx = bias[n], by = bias[n + 1];
            *(float2*)&g_xproj[orow0 * NGC + n] =
                make_float2(acc[mi][ni][0] + bx, acc[mi][ni][1] + by);
            *(float2*)&g_xproj[orow1 * NGC + n] =
                make_float2(acc[mi][ni][2] + bx, acc[mi][ni][3] + by);
        }
    }
}

// ---------------- kernel 2: PERSISTENT recurrence, all 256 steps ----------------
// 128 CTAs, 1/SM. CTA j owns h-cols [8j,8j+8) -> N=32 gate cols.
// Wh slice packed in SMEM once: Bs[n*1028 + ks*32 + l4*8 + kk*2 + half]
//   = Wh[n][ks*32 + kk*8 + l4 + 4*half]  (tf32/RNA). Conflict-free LDS.128 frags.
// h streamed via cp.async.cg, BK=32, double buffer As[2][2grp][128][36].
// Split-K: warps 0-3 -> K[0:512], warps 4-7 -> K[512:1024]. c in registers.
#define P_B_FLOATS (32 * 1028)
#define P_GST (128 * 36)        // one K-group A plane (floats)
#define P_AST (2 * P_GST)       // one double-buffer stage (floats)
#define P_AST_B (P_AST * 4)     // bytes

__global__ void __launch_bounds__(256, 1)
lstm79_run(const float* __restrict__ wh) {
    extern __shared__ float smem[];
    float* Bs = smem;                  // [32][1028] packed Wh
    float* As = smem + P_B_FLOATS;     // [2][2][128][36]

    const int tid = threadIdx.x;
    const int l = tid & 31;
    const int w = tid >> 5;
    const int grp = w >> 2;   // K-half
    const int wrow = w & 3;   // 32-row band
    const int hbase = blockIdx.x * 8;

    // ---- pack Wh slice into smem (tf32, fragment-friendly), once ----
    {
        const float4* wg = (const float4*)wh;
        for (int idx = tid; idx < 32 * 256; idx += 256) {
            int n = idx >> 8;     // 0..31 : gate*8 + hcol
            int c4 = idx & 255;
            long grow = (long)(n >> 3) * HH + hbase + (n & 7);
            float4 u = wg[grow * (HH / 4) + c4];
            float v[4] = {to_tf32(u.x), to_tf32(u.y), to_tf32(u.z), to_tf32(u.w)};
            int k0 = c4 * 4;
#pragma unroll
            for (int e = 0; e < 4; e++) {
                int k = k0 + e;
                int ks = k >> 5, r5 = k & 31;
                int kk = r5 >> 3, t3 = r5 & 7;
                Bs[n * 1028 + ks * 32 + (t3 & 3) * 8 + kk * 2 + (t3 >> 2)] = v[e];
            }
        }
    }
    __syncthreads();

    // ---- cp.async slot mapping: 8 x 16B per thread per stage ----
    uint32_t asb = (uint32_t)__cvta_generic_to_shared(As);
    uint32_t sadr[8];
    int gaoff[8];
#pragma unroll
    for (int i = 0; i < 8; i++) {
        int sl = tid + 256 * i;
        int g = sl >> 10, r = (sl >> 3) & 127, c4 = sl & 7;
        sadr[i] = asb + (uint32_t)((g * P_GST + r * 36 + c4 * 4) * 4);
        gaoff[i] = r * 4096 + g * 2048 + c4 * 16;   // bytes into h
    }

    // ---- fragment base pointers (immediate-offset loads from here on) ----
    const float* A0 = As + grp * P_GST + (wrow * 32 + (l >> 2)) * 36 + (l & 3);
    const float* A1 = A0 + P_AST;
    const float* Bp0 = Bs + (l >> 2) * 1028 + grp * 512 + (l & 3) * 8;

    // pointwise element mapping (4 per thread)
    int eb[4], ehh[4];
#pragma unroll
    for (int i = 0; i < 4; i++) { int e = tid + 256 * i; eb[i] = e >> 3; ehh[i] = e & 7; }

    float* sg0 = As;            // [128][36] grp0 partial gates (buf0 plane0)
    float* sg1 = As + P_GST;    // [128][36] grp1 partial gates (buf0 plane1)
    float cst[4] = {0.f, 0.f, 0.f, 0.f};

    for (int t = 0; t < TT; t++) {
        const float* __restrict__ hin = g_h[t & 1];
        float* __restrict__ hout = g_h[(t + 1) & 1];
        const char* gb = (const char*)hin;

        // prologue: stage 0 into buf0
#pragma unroll
        for (int i = 0; i < 8; i++) cp16(sadr[i], gb + gaoff[i]);
        cp_commit();

        // prefetch this step's xproj slice (consumed in pointwise phase)
        float xp[4][4];
#pragma unroll
        for (int i = 0; i < 4; i++) {
            long base = ((long)t * BB + eb[i]) * NGC + hbase + ehh[i];
#pragma unroll
            for (int g = 0; g < 4; g++) xp[i][g] = __ldcg(&g_xproj[base + (long)g * HH]);
        }

        float acc[2][4][4];
#pragma unroll
        for (int mi = 0; mi < 2; mi++)
#pragma unroll
            for (int ni = 0; ni < 4; ni++)
#pragma unroll
                for (int q = 0; q < 4; q++) acc[mi][ni][q] = 0.f;

        for (int s = 0; s < 16; s++) {
            cp_wait0();
            __syncthreads();
            if (s < 15) {
                const uint32_t boff = (uint32_t)(((s + 1) & 1) * P_AST_B);
                const int goff = (s + 1) * 128;
#pragma unroll
                for (int i = 0; i < 8; i++) cp16(sadr[i] + boff, gb + gaoff[i] + goff);
                cp_commit();
            }
            const float* Ab = (s & 1) ? A1 : A0;
            const float* Bp = Bp0 + s * 32;
#pragma unroll
            for (int kkp = 0; kkp < 2; kkp++) {
                float bq[4][4];
#pragma unroll
                for (int ni = 0; ni < 4; ni++)
                    *(float4*)&bq[ni][0] = *(const float4*)(Bp + ni * 8224 + kkp * 4);
#pragma unroll
                for (int kk2 = 0; kk2 < 2; kk2++) {
                    const int ko = (kkp * 2 + kk2) * 8;
                    uint32_t af[2][4];
#pragma unroll
                    for (int mi = 0; mi < 2; mi++) {
                        af[mi][0] = fasu(Ab[mi * 576 + ko]);
                        af[mi][1] = fasu(Ab[mi * 576 + 288 + ko]);
                        af[mi][2] = fasu(Ab[mi * 576 + ko + 4]);
                        af[mi][3] = fasu(Ab[mi * 576 + 288 + ko + 4]);
                    }
#pragma unroll
                    for (int mi = 0; mi < 2; mi++)
#pragma unroll
                        for (int ni = 0; ni < 4; ni++) {
                            uint32_t bf2[2] = {fasu(bq[ni][kk2 * 2]), fasu(bq[ni][kk2 * 2 + 1])};
                            mma8(acc[mi][ni], af[mi], bf2);
                        }
                }
            }
        }

        // ---- epilogue: both K-groups store to disjoint planes, one sync ----
        {
            float* sgp = grp ? sg1 : sg0;
#pragma unroll
            for (int mi = 0; mi < 2; mi++) {
                int m = wrow * 32 + mi * 16 + (l >> 2);
#pragma unroll
                for (int ni = 0; ni < 4; ni++) {
                    int n = ni * 8 + 2 * (l & 3);
                    *(float2*)&sgp[m * 36 + n] = make_float2(acc[mi][ni][0], acc[mi][ni][1]);
                    *(float2*)&sgp[(m + 8) * 36 + n] = make_float2(acc[mi][ni][2], acc[mi][ni][3]);
                }
            }
        }
        __syncthreads();

        // ---- LSTM pointwise update (c in registers) ----
#pragma unroll
        for (int i = 0; i < 4; i++) {
            const float* gr0 = &sg0[eb[i] * 36];
            const float* gr1 = &sg1[eb[i] * 36];
            float zi = gr0[ehh[i]] + gr1[ehh[i]] + xp[i][0];
            float zf = gr0[8 + ehh[i]] + gr1[8 + ehh[i]] + xp[i][1];
            float zg = gr0[16 + ehh[i]] + gr1[16 + ehh[i]] + xp[i][2];
            float zo = gr0[24 + ehh[i]] + gr1[24 + ehh[i]] + xp[i][3];
            float si = sigm(zi), sf = sigm(zf), tg = tanhx(zg), so = sigm(zo);
            float cn = sf * cst[i] + si * tg;
            cst[i] = cn;
            hout[eb[i] * HH + hbase + ehh[i]] = so * tanhx(cn);
        }

        // ---- grid-wide barrier ----
        __threadfence();   // release hout writes
        __syncthreads();
        if (tid == 0) {
            unsigned int arr = atomicAdd(&g_count, 1u);
            if (arr == (unsigned int)(gridDim.x - 1)) {
                g_count = 0u;
                __threadfence();
                *(volatile unsigned int*)&g_sense = (unsigned int)(t + 1);
            } else {
                while (*(volatile unsigned int*)&g_sense < (unsigned int)(t + 1)) {}
            }
        }
        __syncthreads();
        // no trailing gpu-fence needed: all cross-step global reads are L2-direct
    }
}

// ---------------- kernel 3a: logits = h @ Whp^T + bhp (tiled fp32) ----------------
// smem row stride 33 (conflict-free column reads); global loads are float4,
// smem stores are SCALAR (stride 33 is not 16B-aligned -> no vector stores).
__global__ void __launch_bounds__(256, 1)
lstm79_logits(const float* __restrict__ whp, const float* __restrict__ bhp) {
    __shared__ float hs[32][33];
    __shared__ float ws[64][33];
    const int tid = threadIdx.x;
    const int b0 = blockIdx.x * 32;
    const int o0 = blockIdx.y * 64;
    const int tb = tid & 31;        // batch within tile
    const int to = tid >> 5;        // o-octet within tile

    float acc[8];
#pragma unroll
    for (int j = 0; j < 8; j++) acc[j] = 0.f;

    const int hr = tid >> 3, hc = (tid & 7) * 4;   // hs loader: 4 floats
    const int wr = tid >> 2, wc = (tid & 3) * 8;   // ws loader: 8 floats

    for (int ch = 0; ch < HH / 32; ch++) {
        float4 hv4 = *(const float4*)&g_h[0][(b0 + hr) * HH + ch * 32 + hc];
        hs[hr][hc] = hv4.x; hs[hr][hc + 1] = hv4.y;
        hs[hr][hc + 2] = hv4.z; hs[hr][hc + 3] = hv4.w;
        float4 wv4a = *(const float4*)&whp[(long)(o0 + wr) * HH + ch * 32 + wc];
        float4 wv4b = *(const float4*)&whp[(long)(o0 + wr) * HH + ch * 32 + wc + 4];
        ws[wr][wc] = wv4a.x; ws[wr][wc + 1] = wv4a.y;
        ws[wr][wc + 2] = wv4a.z; ws[wr][wc + 3] = wv4a.w;
        ws[wr][wc + 4] = wv4b.x; ws[wr][wc + 5] = wv4b.y;
        ws[wr][wc + 6] = wv4b.z; ws[wr][wc + 7] = wv4b.w;
        __syncthreads();
#pragma unroll
        for (int k = 0; k < 32; k++) {
            float a = hs[tb][k];
#pragma unroll
            for (int j = 0; j < 8; j++) acc[j] += a * ws[to * 8 + j][k];
        }
        __syncthreads();
    }
#pragma unroll
    for (int j = 0; j < 8; j++)
        g_logits[(long)(b0 + tb) * OO + o0 + to * 8 + j] = acc[j] + bhp[o0 + to * 8 + j];
}

// ---------------- kernel 3b: row softmax ----------------
__global__ void __launch_bounds__(256, 1)
lstm79_smax(float* __restrict__ out) {
    __shared__ float red[8];
    const int b_ = blockIdx.x;
    const int tid = threadIdx.x;

    float lg[4];
#pragma unroll
    for (int j = 0; j < 4; j++) lg[j] = g_logits[(long)b_ * OO + tid + j * 256];

    float mx = fmaxf(fmaxf(lg[0], lg[1]), fmaxf(lg[2], lg[3]));
#pragma unroll
    for (int o = 16; o; o >>= 1) mx = fmaxf(mx, __shfl_xor_sync(0xffffffffu, mx, o));
    if (!(tid & 31)) red[tid >> 5] = mx;
    __syncthreads();
    mx = red[0];
#pragma unroll
    for (int i = 1; i < 8; i++) mx = fmaxf(mx, red[i]);
    __syncthreads();
    float ex[4];
    float se = 0.f;
#pragma unroll
    for (int j = 0; j < 4; j++) { ex[j] = __expf(lg[j] - mx); se += ex[j]; }
#pragma unroll
    for (int o = 16; o; o >>= 1) se += __shfl_xor_sync(0xffffffffu, se, o);
    if (!(tid & 31)) red[tid >> 5] = se;
    __syncthreads();
    se = 0.f;
#pragma unroll
    for (int i = 0; i < 8; i++) se += red[i];
    float inv = 1.f / se;
#pragma unroll
    for (int j = 0; j < 4; j++) out[(long)b_ * OO + tid + j * 256] = ex[j] * inv;
}

// ---------------- host launcher ----------------
extern "C" void kernel_launch(void* const* d_in, const int* in_sizes, int n_in,
                              void* d_out, int out_size) {
    (void)in_sizes; (void)n_in; (void)out_size;
    const float* x   = (const float*)d_in[0];
    const float* Wx  = (const float*)d_in[1];
    const float* Wh  = (const float*)d_in[2];
    const float* bb  = (const float*)d_in[3];
    const float* Whp = (const float*)d_in[4];
    const float* bhp = (const float*)d_in[5];
    float* out = (float*)d_out;

    const int smem1 = (4 * G1_AST) * (int)sizeof(float);               // 73728
    const int smemP = (P_B_FLOATS + 2 * P_AST) * (int)sizeof(float);   // 205312
    cudaFuncSetAttribute(lstm79_xproj, cudaFuncAttributeMaxDynamicSharedMemorySize, smem1);
    cudaFuncSetAttribute(lstm79_run, cudaFuncAttributeMaxDynamicSharedMemorySize, smemP);

    lstm79_init<<<512, 256>>>();
    lstm79_xproj<<<dim3(32, 256), 256, smem1>>>(x, Wx, bb);
    lstm79_run<<<128, 256, smemP>>>(Wh);
    lstm79_logits<<<dim3(BB / 32, OO / 64), 256>>>(Whp, bhp);
    lstm79_smax<<<BB, 256>>>(out);
}

// round 17
// speedup vs baseline: 1.4693x; 1.1943x over previous
#include <cuda_runtime.h>
#include <cstdint>

#define BB 128
#define TT 256
#define DD 512
#define HH 1024
#define OO 1024
#define NGC 4096  // 4*H

// ---------------- device scratch (allocation-free contract) ----------------
__device__ float g_xproj[(size_t)TT * BB * NGC];  // [t][b][4H], 512 MB
__device__ float g_h[2][BB * HH];                 // ping-pong hidden state
__device__ float g_logits[BB * OO];               // pre-softmax logits
__device__ unsigned int g_leaf[8 * 32];           // hierarchical barrier leaves (128B apart)
__device__ unsigned int g_root;                   // hierarchical barrier root
__device__ unsigned int g_sense;                  // barrier generation

// ---------------- helpers ----------------
__device__ __forceinline__ float to_tf32(float x) {
    uint32_t u;
    asm("cvt.rna.tf32.f32 %0, %1;" : "=r"(u) : "f"(x));
    return __uint_as_float(u);
}
__device__ __forceinline__ uint32_t fasu(float x) { return __float_as_uint(x); }

__device__ __forceinline__ void mma8(float* c, const uint32_t* a, uint32_t b0, uint32_t b1) {
    asm volatile(
        "mma.sync.aligned.m16n8k8.row.col.f32.tf32.tf32.f32 "
        "{%0,%1,%2,%3}, {%4,%5,%6,%7}, {%8,%9}, {%0,%1,%2,%3};\n"
        : "+f"(c[0]), "+f"(c[1]), "+f"(c[2]), "+f"(c[3])
        : "r"(a[0]), "r"(a[1]), "r"(a[2]), "r"(a[3]), "r"(b0), "r"(b1));
}

__device__ __forceinline__ void cp16(uint32_t saddr, const void* gaddr) {
    asm volatile("cp.async.cg.shared.global [%0], [%1], 16;\n" :: "r"(saddr), "l"(gaddr));
}
__device__ __forceinline__ void cp_commit() {
    asm volatile("cp.async.commit_group;\n" ::: "memory");
}
__device__ __forceinline__ void cp_wait2() {
    asm volatile("cp.async.wait_group 2;\n" ::: "memory");
}

__device__ __forceinline__ float sigm(float x) { return 1.f / (1.f + __expf(-x)); }
__device__ __forceinline__ float tanhx(float x) { return 1.f - 2.f / (1.f + __expf(2.f * x)); }

// ---------------- init: zero h0 and barrier state ----------------
__global__ void lstm79_init() {
    int i = blockIdx.x * blockDim.x + threadIdx.x;  // 512*256 = BB*HH exactly
    g_h[0][i] = 0.f;
    if (i < 256) g_leaf[i] = 0u;
    if (i == 0) { g_root = 0u; g_sense = 0u; }
}

// ---------------- kernel 1: xproj = x @ Wx^T + b, scattered to [t][b][4H] ----
#define G1_LD 36
#define G1_AST (128 * G1_LD)

__global__ void __launch_bounds__(256, 1)
lstm79_xproj(const float* __restrict__ x, const float* __restrict__ wx,
             const float* __restrict__ bias) {
    extern __shared__ float smem[];
    float* As = smem;               // [2][128][36]
    float* Bs = smem + 2 * G1_AST;  // [2][128][36]

    const int tid = threadIdx.x;
    const int l = tid & 31;
    const int w = tid >> 5;
    const int wm = w >> 2;
    const int wn = w & 3;
    const int row0 = blockIdx.y * 128;
    const int col0 = blockIdx.x * 128;

    int rA[4], cA[4];
    long abase[4], bbase[4];
#pragma unroll
    for (int i = 0; i < 4; i++) {
        int s = tid + 256 * i;
        rA[i] = s >> 3;
        cA[i] = s & 7;
        abase[i] = (long)(row0 + rA[i]) * (DD / 4) + cA[i];
        bbase[i] = (long)(col0 + rA[i]) * (DD / 4) + cA[i];
    }
    const float4* xg = (const float4*)x;
    const float4* wg = (const float4*)wx;

    float acc[4][4][4];
#pragma unroll
    for (int mi = 0; mi < 4; mi++)
#pragma unroll
        for (int ni = 0; ni < 4; ni++)
#pragma unroll
            for (int q = 0; q < 4; q++) acc[mi][ni][q] = 0.f;

    const int NSTAGE = DD / 32;  // 16
    float4 ra[4], rb[4];

#pragma unroll
    for (int i = 0; i < 4; i++) { ra[i] = xg[abase[i]]; rb[i] = wg[bbase[i]]; }
#pragma unroll
    for (int i = 0; i < 4; i++) {
        float4 v = ra[i];
        v.x = to_tf32(v.x); v.y = to_tf32(v.y); v.z = to_tf32(v.z); v.w = to_tf32(v.w);
        *(float4*)&As[rA[i] * G1_LD + cA[i] * 4] = v;
        float4 u = rb[i];
        u.x = to_tf32(u.x); u.y = to_tf32(u.y); u.z = to_tf32(u.z); u.w = to_tf32(u.w);
        *(float4*)&Bs[rA[i] * G1_LD + cA[i] * 4] = u;
    }

    const int aoff = (wm * 64 + (l >> 2)) * G1_LD + (l & 3);
    const int boff = (wn * 32 + (l >> 2)) * G1_LD + (l & 3);

    for (int s = 0; s < NSTAGE; s++) {
        __syncthreads();
        if (s + 1 < NSTAGE) {
#pragma unroll
            for (int i = 0; i < 4; i++) {
                ra[i] = xg[abase[i] + (long)(s + 1) * 8];
                rb[i] = wg[bbase[i] + (long)(s + 1) * 8];
            }
        }
        const float* pA = As + (s & 1) * G1_AST + aoff;
        const float* pB = Bs + (s & 1) * G1_AST + boff;
#pragma unroll
        for (int kk = 0; kk < 4; kk++) {
            uint32_t af[4][4], bf[4][2];
            const int ko = kk * 8;
#pragma unroll
            for (int mi = 0; mi < 4; mi++) {
                af[mi][0] = fasu(pA[mi * 576 + ko]);
                af[mi][1] = fasu(pA[mi * 576 + 288 + ko]);
                af[mi][2] = fasu(pA[mi * 576 + ko + 4]);
                af[mi][3] = fasu(pA[mi * 576 + 288 + ko + 4]);
            }
#pragma unroll
            for (int ni = 0; ni < 4; ni++) {
                bf[ni][0] = fasu(pB[ni * 288 + ko]);
                bf[ni][1] = fasu(pB[ni * 288 + ko + 4]);
            }
#pragma unroll
            for (int mi = 0; mi < 4; mi++)
#pragma unroll
                for (int ni = 0; ni < 4; ni++)
                    mma8(acc[mi][ni], af[mi], bf[ni][0], bf[ni][1]);
        }
        if (s + 1 < NSTAGE) {
            const int nb = (s + 1) & 1;
#pragma unroll
            for (int i = 0; i < 4; i++) {
                float4 v = ra[i];
                v.x = to_tf32(v.x); v.y = to_tf32(v.y); v.z = to_tf32(v.z); v.w = to_tf32(v.w);
                *(float4*)&As[nb * G1_AST + rA[i] * G1_LD + cA[i] * 4] = v;
                float4 u = rb[i];
                u.x = to_tf32(u.x); u.y = to_tf32(u.y); u.z = to_tf32(u.z); u.w = to_tf32(u.w);
                *(float4*)&Bs[nb * G1_AST + rA[i] * G1_LD + cA[i] * 4] = u;
            }
        }
    }

    // epilogue: scatter (b,t) row -> out row t*B+b, add bias
#pragma unroll
    for (int mi = 0; mi < 4; mi++) {
        int m = row0 + wm * 64 + mi * 16 + (l >> 2);
        long orow0 = (long)(m & 255) * BB + (m >> 8);
        int m2 = m + 8;
        long orow1 = (long)(m2 & 255) * BB + (m2 >> 8);
#pragma unroll
        for (int ni = 0; ni < 4; ni++) {
            int n = col0 + wn * 32 + ni * 8 + 2 * (l & 3);
            float bx = bias[n], by = bias[n + 1];
            *(float2*)&g_xproj[orow0 * NGC + n] =
                make_float2(acc[mi][ni][0] + bx, acc[mi][ni][1] + by);
            *(float2*)&g_xproj[orow1 * NGC + n] =
                make_float2(acc[mi][ni][2] + bx, acc[mi][ni][3] + by);
        }
    }
}

// ---------------- kernel 2: PERSISTENT recurrence, warp-autonomous ----------
// 128 CTAs, 1/SM. CTA j owns h-cols [8j,8j+8) -> N=32 gate cols (4 gates x 8h).
// Warp w owns batch rows [16w,16w+16), full K=1024. No split-K, no mainloop
// syncthreads. Wh tf32 packed in SMEM (R13 layout, LDS.128 B-frags).
// A: per-warp private 4-slot cp.async ring, slot = 16 rows x BK32 (stride 36),
// wait_group 2 => prefetch depth 3. Gates/cell state fully in registers.
#define WH_FLOATS (32 * 1028)          // 131584 B
#define SLOT_B 2304                    // 16*36*4
#define NRING 4
#define WARP_RING_B (NRING * SLOT_B)   // 9216
#define SMEMP_BYTES (WH_FLOATS * 4 + 8 * WARP_RING_B)  // 205312

__global__ void __launch_bounds__(256, 1)
lstm79_run(const float* __restrict__ wh) {
    extern __shared__ float smem[];
    float* Bs = smem;                              // packed Wh tf32
    char* ring = (char*)(smem + WH_FLOATS);        // 8 warp-private rings

    const int tid = threadIdx.x;
    const int l = tid & 31;
    const int w = tid >> 5;
    const int hbase = blockIdx.x * 8;

    // ---- pack Wh slice -> smem (tf32, fragment-friendly), once ----
    for (int idx = tid; idx < 32 * 1024; idx += 256) {
        int n = idx >> 10, k = idx & 1023;
        long grow = (long)(n >> 3) * HH + hbase + (n & 7);
        float v = to_tf32(wh[grow * HH + k]);
        int ks = k >> 5, r5 = k & 31;
        int kk = r5 >> 3, t3 = r5 & 7;
        Bs[n * 1028 + ks * 32 + (t3 & 3) * 8 + kk * 2 + (t3 >> 2)] = v;
    }
    __syncthreads();

    // ---- per-warp ring addressing ----
    char* wring = ring + w * WARP_RING_B;
    const uint32_t sbase = (uint32_t)__cvta_generic_to_shared(wring) +
                           (uint32_t)((l >> 3) * 144 + (l & 7) * 16);
    const int R0 = w * 16;
    int gaoff[4];
#pragma unroll
    for (int j = 0; j < 4; j++)
        gaoff[j] = (R0 + (l >> 3) + 4 * j) * 4096 + (l & 7) * 16;  // bytes

    // fragment base pointers
    const float* pA0 = (const float*)wring + (l >> 2) * 36 + (l & 3);
    const float* pB0 = Bs + (l >> 2) * 1028 + (l & 3) * 8;

    // pointwise mapping: rows r0, r0+8 ; h-cols 2*(l&3), +1
    const int r0 = R0 + (l >> 2);
    const int hh0 = 2 * (l & 3);

    float cst[4] = {0.f, 0.f, 0.f, 0.f};  // [row(2)][hh(2)]

    for (int t = 0; t < TT; t++) {
        const char* gb = (const char*)g_h[t & 1];
        float* hob = g_h[(t + 1) & 1];

        // prologue: stages 0..2 into slots 0..2 (3 groups)
#pragma unroll
        for (int p = 0; p < 3; p++) {
#pragma unroll
            for (int j = 0; j < 4; j++)
                cp16(sbase + (uint32_t)(p * SLOT_B + j * 576), gb + gaoff[j] + p * 128);
            cp_commit();
        }

        // xproj prefetch: 2 rows x 4 gates, float2 each
        float2 xp[2][4];
        {
            const float* xb0 = &g_xproj[((long)t * BB + r0) * NGC + hbase + hh0];
            const float* xb1 = xb0 + 8 * NGC;
#pragma unroll
            for (int g = 0; g < 4; g++) {
                xp[0][g] = __ldcg((const float2*)(xb0 + g * HH));
                xp[1][g] = __ldcg((const float2*)(xb1 + g * HH));
            }
        }

        float acc[4][4];
#pragma unroll
        for (int ni = 0; ni < 4; ni++)
#pragma unroll
            for (int q = 0; q < 4; q++) acc[ni][q] = 0.f;

        for (int s = 0; s < 32; s++) {
            cp_wait2();                 // own group for stage s complete
            if (s < 29) {               // prefetch stage s+3 into slot (s+3)&3
                const uint32_t so = sbase + (uint32_t)(((s + 3) & 3) * SLOT_B);
                const char* gg = gb + (s + 3) * 128;
#pragma unroll
                for (int j = 0; j < 4; j++) cp16(so + (uint32_t)(j * 576), gg + gaoff[j]);
            }
            cp_commit();

            const float* pA = pA0 + (s & 3) * (SLOT_B / 4);
            const float* pB = pB0 + s * 32;
#pragma unroll
            for (int kkp = 0; kkp < 2; kkp++) {
                float4 bq[4];
#pragma unroll
                for (int ni = 0; ni < 4; ni++)
                    bq[ni] = *(const float4*)(pB + ni * 8224 + kkp * 4);
#pragma unroll
                for (int kk2 = 0; kk2 < 2; kk2++) {
                    const int ko = (kkp * 2 + kk2) * 8;
                    uint32_t af[4];
                    af[0] = fasu(pA[ko]);
                    af[1] = fasu(pA[288 + ko]);
                    af[2] = fasu(pA[ko + 4]);
                    af[3] = fasu(pA[288 + ko + 4]);
#pragma unroll
                    for (int ni = 0; ni < 4; ni++) {
                        uint32_t b0 = kk2 ? fasu(bq[ni].z) : fasu(bq[ni].x);
                        uint32_t b1 = kk2 ? fasu(bq[ni].w) : fasu(bq[ni].y);
                        mma8(acc[ni], af, b0, b1);
                    }
                }
            }
        }

        // ---- pointwise LSTM update, fully in registers ----
#pragma unroll
        for (int rr = 0; rr < 2; rr++) {
            float hv[2];
#pragma unroll
            for (int e = 0; e < 2; e++) {
                const int q = rr * 2 + e;
                float zi = acc[0][q] + (e ? xp[rr][0].y : xp[rr][0].x);
                float zf = acc[1][q] + (e ? xp[rr][1].y : xp[rr][1].x);
                float zg = acc[2][q] + (e ? xp[rr][2].y : xp[rr][2].x);
                float zo = acc[3][q] + (e ? xp[rr][3].y : xp[rr][3].x);
                float si = sigm(zi), sf = sigm(zf), tg = tanhx(zg), so_ = sigm(zo);
                float cn = sf * cst[q] + si * tg;
                cst[q] = cn;
                hv[e] = so_ * tanhx(cn);
            }
            *(float2*)&hob[(r0 + rr * 8) * HH + hbase + hh0] = make_float2(hv[0], hv[1]);
        }

        // ---- grid-wide hierarchical barrier ----
        __threadfence();
        __syncthreads();
        if (tid == 0) {
            const unsigned grpi = blockIdx.x >> 4;  // 8 groups of 16 CTAs
            unsigned v = atomicAdd(&g_leaf[grpi * 32], 1u) + 1u;
            if (v == 16u * (unsigned)(t + 1)) {
                unsigned r = atomicAdd(&g_root, 1u) + 1u;
                if (r == 8u * (unsigned)(t + 1)) {
                    __threadfence();
                    *(volatile unsigned int*)&g_sense = (unsigned)(t + 1);
                } else {
                    while (*(volatile unsigned int*)&g_sense < (unsigned)(t + 1)) {}
                }
            } else {
                while (*(volatile unsigned int*)&g_sense < (unsigned)(t + 1)) {}
            }
        }
        __syncthreads();
    }
}

// ---------------- kernel 3a: logits = h @ Whp^T + bhp (fp32 tiled) ------------
__global__ void __launch_bounds__(256, 1)
lstm79_logits(const float* __restrict__ whp, const float* __restrict__ bhp) {
    __shared__ float hs[32][33];
    __shared__ float ws[64][33];
    const int tid = threadIdx.x;
    const int b0 = blockIdx.x * 32;
    const int o0 = blockIdx.y * 64;
    const int tb = tid & 31;
    const int to = tid >> 5;

    float acc[8];
#pragma unroll
    for (int j = 0; j < 8; j++) acc[j] = 0.f;

    const int hr = tid >> 3, hc = (tid & 7) * 4;
    const int wr = tid >> 2, wc = (tid & 3) * 8;

    for (int ch = 0; ch < HH / 32; ch++) {
        float4 hv4 = *(const float4*)&g_h[0][(b0 + hr) * HH + ch * 32 + hc];
        hs[hr][hc] = hv4.x; hs[hr][hc + 1] = hv4.y;
        hs[hr][hc + 2] = hv4.z; hs[hr][hc + 3] = hv4.w;
        float4 wv4a = *(const float4*)&whp[(long)(o0 + wr) * HH + ch * 32 + wc];
        float4 wv4b = *(const float4*)&whp[(long)(o0 + wr) * HH + ch * 32 + wc + 4];
        ws[wr][wc] = wv4a.x; ws[wr][wc + 1] = wv4a.y;
        ws[wr][wc + 2] = wv4a.z; ws[wr][wc + 3] = wv4a.w;
        ws[wr][wc + 4] = wv4b.x; ws[wr][wc + 5] = wv4b.y;
        ws[wr][wc + 6] = wv4b.z; ws[wr][wc + 7] = wv4b.w;
        __syncthreads();
#pragma unroll
        for (int k = 0; k < 32; k++) {
            float a = hs[tb][k];
#pragma unroll
            for (int j = 0; j < 8; j++) acc[j] += a * ws[to * 8 + j][k];
        }
        __syncthreads();
    }
#pragma unroll
    for (int j = 0; j < 8; j++)
        g_logits[(long)(b0 + tb) * OO + o0 + to * 8 + j] = acc[j] + bhp[o0 + to * 8 + j];
}

// ---------------- kernel 3b: row softmax ----------------
__global__ void __launch_bounds__(256, 1)
lstm79_smax(float* __restrict__ out) {
    __shared__ float red[8];
    const int b_ = blockIdx.x;
    const int tid = threadIdx.x;

    float lg[4];
#pragma unroll
    for (int j = 0; j < 4; j++) lg[j] = g_logits[(long)b_ * OO + tid + j * 256];

    float mx = fmaxf(fmaxf(lg[0], lg[1]), fmaxf(lg[2], lg[3]));
#pragma unroll
    for (int o = 16; o; o >>= 1) mx = fmaxf(mx, __shfl_xor_sync(0xffffffffu, mx, o));
    if (!(tid & 31)) red[tid >> 5] = mx;
    __syncthreads();
    mx = red[0];
#pragma unroll
    for (int i = 1; i < 8; i++) mx = fmaxf(mx, red[i]);
    __syncthreads();
    float ex[4];
    float se = 0.f;
#pragma unroll
    for (int j = 0; j < 4; j++) { ex[j] = __expf(lg[j] - mx); se += ex[j]; }
#pragma unroll
    for (int o = 16; o; o >>= 1) se += __shfl_xor_sync(0xffffffffu, se, o);
    if (!(tid & 31)) red[tid >> 5] = se;
    __syncthreads();
    se = 0.f;
#pragma unroll
    for (int i = 0; i < 8; i++) se += red[i];
    float inv = 1.f / se;
#pragma unroll
    for (int j = 0; j < 4; j++) out[(long)b_ * OO + tid + j * 256] = ex[j] * inv;
}

// ---------------- host launcher ----------------
extern "C" void kernel_launch(void* const* d_in, const int* in_sizes, int n_in,
                              void* d_out, int out_size) {
    (void)in_sizes; (void)n_in; (void)out_size;
    const float* x   = (const float*)d_in[0];
    const float* Wx  = (const float*)d_in[1];
    const float* Wh  = (const float*)d_in[2];
    const float* bb  = (const float*)d_in[3];
    const float* Whp = (const float*)d_in[4];
    const float* bhp = (const float*)d_in[5];
    float* out = (float*)d_out;

    const int smem1 = (4 * G1_AST) * (int)sizeof(float);  // 73728
    const int smemP = SMEMP_BYTES;                        // 205312
    cudaFuncSetAttribute(lstm79_xproj, cudaFuncAttributeMaxDynamicSharedMemorySize, smem1);
    cudaFuncSetAttribute(lstm79_run, cudaFuncAttributeMaxDynamicSharedMemorySize, smemP);

    lstm79_init<<<512, 256>>>();
    lstm79_xproj<<<dim3(32, 256), 256, smem1>>>(x, Wx, bb);
    lstm79_run<<<128, 256, smemP>>>(Wh);
    lstm79_logits<<<dim3(BB / 32, OO / 64), 256>>>(Whp, bhp);
    lstm79_smax<<<BB, 256>>>(out);
}